// round 2
// baseline (speedup 1.0000x reference)
#include <cuda_runtime.h>
#include <cstdint>

#define B_N 4
#define T_N 20000
#define E_N 2000
#define I_N 500
#define SUB 20
#define HID 10
#define COS 24
#define TNO 200

typedef unsigned long long ull;

// ---------------- scratch (static device globals; no allocation) ----------------
__device__ float  g_syn_e[B_N * SUB * T_N];
__device__ float  g_syn_i[B_N * SUB * T_N];
__device__ float2 g_Wpe[E_N * 10];          // packed sub-pair weights (C*exp(scale))
__device__ float2 g_Wpi[I_N * 10];
__device__ float2 g_KEp[SUB * TNO * 5];     // combined conv kernels, h-pairs packed
__device__ float2 g_KIp[SUB * TNO * 5];
__device__ float  g_expW2[SUB * HID];
__device__ float2 g_biasP[SUB * 5];
__device__ float  g_sub_scratch[B_N * T_N * SUB];
__device__ float  g_Ce_scratch[SUB * E_N];
__device__ float  g_Ci_scratch[SUB * I_N];

// ---------------- f32x2 packed-math helpers (sm_103a) ----------------
__device__ __forceinline__ ull pack2(float x, float y) {
    ull r; asm("mov.b64 %0,{%1,%2};" : "=l"(r) : "f"(x), "f"(y)); return r;
}
__device__ __forceinline__ ull fma2(ull a, ull b, ull c) {
    ull d; asm("fma.rn.f32x2 %0,%1,%2,%3;" : "=l"(d) : "l"(a), "l"(b), "l"(c)); return d;
}
__device__ __forceinline__ void unpack2(ull v, float& x, float& y) {
    asm("mov.b64 {%0,%1},%2;" : "=f"(x), "=f"(y) : "l"(v));
}

// ---------------- kernel 1: column softmax over subs + packed weight build ----------------
__global__ void softmax_kernel(const float* __restrict__ raw, const float* __restrict__ g,
                               const float* __restrict__ lsc, const int* __restrict__ testp,
                               int N, int isE, float* dout, int out_size)
{
    int e = blockIdx.x * blockDim.x + threadIdx.x;
    if (e >= N) return;
    int test = *testp;
    float sc = test ? 10000.f : 1000.f;
    float v[SUB];
    float m = -1e30f;
#pragma unroll
    for (int s = 0; s < SUB; s++) {
        float x = raw[s * N + e];
        if (!test) x += g[s * N + e];
        x *= sc;
        v[s] = x;
        m = fmaxf(m, x);
    }
    float sum = 0.f;
#pragma unroll
    for (int s = 0; s < SUB; s++) { v[s] = expf(v[s] - m); sum += v[s]; }
    float inv = 1.f / sum;
#pragma unroll
    for (int s = 0; s < SUB; s++) v[s] *= inv;

    // write C_syn output
    float* cdst;
    if (out_size == 1730000) cdst = dout + (isE ? 1680000 : 1720000);
    else                     cdst = isE ? g_Ce_scratch : g_Ci_scratch;
#pragma unroll
    for (int s = 0; s < SUB; s++) cdst[s * N + e] = v[s];

    float ex = expf(lsc[e]);
    float2* wp = isE ? g_Wpe : g_Wpi;
#pragma unroll
    for (int p = 0; p < 10; p++)
        wp[e * 10 + p] = make_float2(v[2 * p] * ex, v[2 * p + 1] * ex);
}

// ---------------- kernel 2: fold basis into 200-tap conv kernels ----------------
__device__ __forceinline__ float basisv(int k, int d) {
    const float PI = 3.14159265358979f;
    float raw = 6.f * logf((float)d + 1.f + 1e-7f);
    float phi = 1.57079632679f * (float)k;
    if (raw >= phi - PI && raw <= phi + PI) return 0.5f * cosf(raw - phi) + 0.5f;
    return 0.f;
}

__global__ void prep_kernel(const float* __restrict__ We, const float* __restrict__ Wi,
                            const float* __restrict__ W2, const float* __restrict__ b1)
{
    int i = blockIdx.x * blockDim.x + threadIdx.x;
    if (i < SUB * HID) g_expW2[i] = expf(W2[i]);
    if (i < SUB * 5)   g_biasP[i] = make_float2(b1[2 * i], b1[2 * i + 1]);
    if (i >= 2 * SUB * 5 * TNO) return;
    int which = i / (SUB * 5 * TNO);
    int r = i % (SUB * 5 * TNO);
    int d = r % TNO; r /= TNO;
    int p = r % 5;
    int s = r / 5;
    const float* W = which ? Wi : We;
    float k0 = 0.f, k1 = 0.f;
#pragma unroll
    for (int k = 0; k < COS; k++) {
        float bv = basisv(k, d);
        k0 += bv * W[(s * HID + 2 * p) * COS + k];
        k1 += bv * W[(s * HID + 2 * p + 1) * COS + k];
    }
    float2* dst = which ? g_KIp : g_KEp;
    dst[(s * TNO + d) * 5 + p] = make_float2(k0, k1);
}

// ---------------- kernel 3: syn = S @ W^T  ([80000 x K] x [K x 20]) ----------------
__global__ void __launch_bounds__(128, 8) gemm_kernel(const float* __restrict__ S, int K, int isE)
{
    __shared__ float sS[128][21];   // pad to stride 21: conflict-free column reads
    __shared__ ull   sW[20][10];
    const ull* Wp = reinterpret_cast<const ull*>(isE ? g_Wpe : g_Wpi);
    float* syn = isE ? g_syn_e : g_syn_i;
    int tid = threadIdx.x;
    int rowBase = blockIdx.x * 128;

    ull acc[10];
#pragma unroll
    for (int p = 0; p < 10; p++) acc[p] = 0ull;

    int nCh = K / 20;
    for (int c = 0; c < nCh; c++) {
        // stage S tile [128 x 20] with float4 loads
#pragma unroll
        for (int idx = tid; idx < 640; idx += 128) {
            int row = idx / 5, q = idx % 5;
            const float4* p4 = reinterpret_cast<const float4*>(
                S + (size_t)(rowBase + row) * K + c * 20 + q * 4);
            float4 v = *p4;
            float* dstp = &sS[row][q * 4];
            dstp[0] = v.x; dstp[1] = v.y; dstp[2] = v.z; dstp[3] = v.w;
        }
        for (int idx = tid; idx < 200; idx += 128)
            sW[idx / 10][idx % 10] = Wp[(c * 20 + idx / 10) * 10 + idx % 10];
        __syncthreads();
#pragma unroll
        for (int j = 0; j < 20; j++) {
            float v = sS[tid][j];
            ull vv = pack2(v, v);
#pragma unroll
            for (int p = 0; p < 10; p++) acc[p] = fma2(vv, sW[j][p], acc[p]);
        }
        __syncthreads();
    }

    int r = rowBase + tid;
    int b = r / T_N;
    int t = r % T_N;
    float* outp = syn + (size_t)b * SUB * T_N + t;
#pragma unroll
    for (int p = 0; p < 10; p++) {
        float h0, h1; unpack2(acc[p], h0, h1);
        outp[(size_t)(2 * p) * T_N] = h0;
        outp[(size_t)(2 * p + 1) * T_N] = h1;
    }
}

// ---------------- kernel 4: 200-tap causal conv (e+i) + tanh + layer2 reduce ----------------
__global__ void __launch_bounds__(256, 4) conv_kernel(float* __restrict__ dout, int out_size)
{
    __shared__ float sE[712], sI[712];
    __shared__ ull sKE[1000], sKI[1000];
    int tid = threadIdx.x;
    int s = blockIdx.y, b = blockIdx.z;
    int t0 = blockIdx.x * 512;

    const float* se = g_syn_e + (size_t)(b * SUB + s) * T_N;
    const float* si = g_syn_i + (size_t)(b * SUB + s) * T_N;
    for (int l = tid; l < 712; l += 256) {
        int t = t0 - 199 + l;
        bool ok = (t >= 0 && t < T_N);
        sE[l] = ok ? se[t] : 0.f;
        sI[l] = ok ? si[t] : 0.f;
    }
    const ull* KE = reinterpret_cast<const ull*>(g_KEp) + (size_t)s * 1000;
    const ull* KI = reinterpret_cast<const ull*>(g_KIp) + (size_t)s * 1000;
    for (int l = tid; l < 1000; l += 256) { sKE[l] = KE[l]; sKI[l] = KI[l]; }
    __syncthreads();

    float* subdst = (out_size == 1730000) ? (dout + 80000) : g_sub_scratch;
    float ew[10];
#pragma unroll
    for (int h = 0; h < 10; h++) ew[h] = g_expW2[s * 10 + h];

    for (int rep = 0; rep < 2; rep++) {
        int tl = tid + rep * 256;
        int t = t0 + tl;
        if (t >= T_N) continue;
        ull acc[5];
#pragma unroll
        for (int p = 0; p < 5; p++) {
            float2 bp = g_biasP[s * 5 + p];
            acc[p] = pack2(bp.x, bp.y);
        }
        int base = tl + 199;
#pragma unroll 2
        for (int d = 0; d < 200; d++) {
            float ve = sE[base - d], vi = sI[base - d];
            ull ve2 = pack2(ve, ve), vi2 = pack2(vi, vi);
#pragma unroll
            for (int p = 0; p < 5; p++) acc[p] = fma2(ve2, sKE[d * 5 + p], acc[p]);
#pragma unroll
            for (int p = 0; p < 5; p++) acc[p] = fma2(vi2, sKI[d * 5 + p], acc[p]);
        }
        float res = 0.f;
#pragma unroll
        for (int p = 0; p < 5; p++) {
            float h0, h1; unpack2(acc[p], h0, h1);
            res += tanhf(h0) * ew[2 * p] + tanhf(h1) * ew[2 * p + 1];
        }
        subdst[((size_t)b * T_N + t) * SUB + s] = res;
    }
}

// ---------------- kernel 5: final[b,t] = sum_s sub_out + V_o ----------------
__global__ void final_kernel(float* dout, int out_size, const float* __restrict__ Vo)
{
    int idx = blockIdx.x * blockDim.x + threadIdx.x;
    if (idx >= B_N * T_N) return;
    const float* src = (out_size == 1730000) ? (dout + 80000) : g_sub_scratch;
    const float* p = src + (size_t)idx * SUB;
    float sum = 0.f;
#pragma unroll
    for (int i = 0; i < SUB; i++) sum += p[i];
    dout[idx] = sum + Vo[0];
}

// ---------------- launch ----------------
extern "C" void kernel_launch(void* const* d_in, const int* in_sizes, int n_in,
                              void* d_out, int out_size)
{
    const float* S_e     = (const float*)d_in[0];
    const float* S_i     = (const float*)d_in[1];
    const int*   testp   = (const int*)  d_in[3];
    const float* g_e     = (const float*)d_in[4];
    const float* g_i     = (const float*)d_in[5];
    const float* E_scale = (const float*)d_in[6];
    const float* I_scale = (const float*)d_in[7];
    const float* We      = (const float*)d_in[8];
    const float* Wi      = (const float*)d_in[9];
    const float* W2      = (const float*)d_in[10];
    const float* b1      = (const float*)d_in[11];
    const float* Ce      = (const float*)d_in[12];
    const float* Ci      = (const float*)d_in[13];
    const float* Vo      = (const float*)d_in[14];
    float* out = (float*)d_out;

    softmax_kernel<<<(E_N + 127) / 128, 128>>>(Ce, g_e, E_scale, testp, E_N, 1, out, out_size);
    softmax_kernel<<<(I_N + 127) / 128, 128>>>(Ci, g_i, I_scale, testp, I_N, 0, out, out_size);
    prep_kernel<<<(2 * SUB * 5 * TNO + 255) / 256, 256>>>(We, Wi, W2, b1);
    gemm_kernel<<<(B_N * T_N) / 128, 128>>>(S_e, E_N, 1);
    gemm_kernel<<<(B_N * T_N) / 128, 128>>>(S_i, I_N, 0);
    dim3 cg(40, SUB, B_N);
    conv_kernel<<<cg, 256>>>(out, out_size);
    final_kernel<<<(B_N * T_N + 255) / 256, 256>>>(out, out_size, Vo);
}

// round 4
// speedup vs baseline: 1.3763x; 1.3763x over previous
#include <cuda_runtime.h>
#include <cstdint>

#define B_N 4
#define T_N 20000
#define E_N 2000
#define I_N 500
#define SUB 20
#define HID 10
#define COS 24
#define TNO 200

typedef unsigned long long ull;

// ---------------- scratch (static device globals; no allocation) ----------------
__device__ float  g_syn_e[B_N * SUB * T_N];
__device__ float  g_syn_i[B_N * SUB * T_N];
__device__ ull    g_Wpe[E_N * 10];          // packed sub-pair weights (C*exp(scale))
__device__ ull    g_Wpi[I_N * 10];
__device__ ull    g_Kp[SUB * TNO * 10];     // combined conv taps: [s][d][p], p<5 E-pairs, p>=5 I-pairs
__device__ float  g_expW2[SUB * HID];
__device__ ull    g_biasP[SUB * 5];
__device__ float  g_sub_scratch[B_N * T_N * SUB];
__device__ float  g_Ce_scratch[SUB * E_N];
__device__ float  g_Ci_scratch[SUB * I_N];

// ---------------- f32x2 packed-math helpers (sm_103a) ----------------
__device__ __forceinline__ ull pack2(float x, float y) {
    ull r; asm("mov.b64 %0,{%1,%2};" : "=l"(r) : "f"(x), "f"(y)); return r;
}
__device__ __forceinline__ ull fma2(ull a, ull b, ull c) {
    ull d; asm("fma.rn.f32x2 %0,%1,%2,%3;" : "=l"(d) : "l"(a), "l"(b), "l"(c)); return d;
}
__device__ __forceinline__ void unpack2(ull v, float& x, float& y) {
    asm("mov.b64 {%0,%1},%2;" : "=f"(x), "=f"(y) : "l"(v));
}

// ---------------- kernel 1: column softmax over subs + packed weight build ----------------
__global__ void softmax_kernel(const float* __restrict__ raw, const float* __restrict__ g,
                               const float* __restrict__ lsc, const int* __restrict__ testp,
                               int N, int isE, float* dout, int out_size)
{
    int e = blockIdx.x * blockDim.x + threadIdx.x;
    if (e >= N) return;
    int test = *testp;
    float sc = test ? 10000.f : 1000.f;
    float v[SUB];
    float m = -1e30f;
#pragma unroll
    for (int s = 0; s < SUB; s++) {
        float x = raw[s * N + e];
        if (!test) x += g[s * N + e];
        x *= sc;
        v[s] = x;
        m = fmaxf(m, x);
    }
    float sum = 0.f;
#pragma unroll
    for (int s = 0; s < SUB; s++) { v[s] = expf(v[s] - m); sum += v[s]; }
    float inv = 1.f / sum;
#pragma unroll
    for (int s = 0; s < SUB; s++) v[s] *= inv;

    float* cdst;
    if (out_size == 1730000) cdst = dout + (isE ? 1680000 : 1720000);
    else                     cdst = isE ? g_Ce_scratch : g_Ci_scratch;
#pragma unroll
    for (int s = 0; s < SUB; s++) cdst[s * N + e] = v[s];

    float ex = expf(lsc[e]);
    ull* wp = isE ? g_Wpe : g_Wpi;
#pragma unroll
    for (int p = 0; p < 10; p++)
        wp[e * 10 + p] = pack2(v[2 * p] * ex, v[2 * p + 1] * ex);
}

// ---------------- kernel 2: fold basis into combined 200-tap conv kernels ----------------
__device__ __forceinline__ float basisv(int k, int d) {
    const float PI = 3.14159265358979f;
    float raw = 6.f * logf((float)d + 1.f + 1e-7f);
    float phi = 1.57079632679f * (float)k;
    if (raw >= phi - PI && raw <= phi + PI) return 0.5f * cosf(raw - phi) + 0.5f;
    return 0.f;
}

__global__ void prep_kernel(const float* __restrict__ We, const float* __restrict__ Wi,
                            const float* __restrict__ W2, const float* __restrict__ b1)
{
    int i = blockIdx.x * blockDim.x + threadIdx.x;
    if (i < SUB * HID) g_expW2[i] = expf(W2[i]);
    if (i < SUB * 5)   g_biasP[i] = pack2(b1[2 * i], b1[2 * i + 1]);
    if (i >= SUB * TNO * 10) return;
    int s = i / (TNO * 10);
    int r = i % (TNO * 10);
    int d = r / 10;
    int p = r % 10;
    const float* W = (p < 5) ? We : Wi;
    int pp = (p < 5) ? p : (p - 5);
    float k0 = 0.f, k1 = 0.f;
#pragma unroll
    for (int k = 0; k < COS; k++) {
        float bv = basisv(k, d);
        k0 += bv * W[(s * HID + 2 * pp) * COS + k];
        k1 += bv * W[(s * HID + 2 * pp + 1) * COS + k];
    }
    g_Kp[(s * TNO + d) * 10 + p] = pack2(k0, k1);
}

// ---------------- kernel 3: syn = S @ W^T  merged E/I, register double-buffered ----------------
__global__ void __launch_bounds__(128) gemm_kernel(const float* __restrict__ SE,
                                                   const float* __restrict__ SI)
{
    __shared__ float sS[2][128][21];  // stride 21: conflict-free per-thread column reads
    __shared__ ull   sW[2][200];
    int isE = (blockIdx.y == 0);
    const float* S  = isE ? SE : SI;
    int K           = isE ? E_N : I_N;
    int nCh         = K / 20;
    const ull* Wp   = isE ? g_Wpe : g_Wpi;
    float* syn      = isE ? g_syn_e : g_syn_i;

    int tid = threadIdx.x;
    int rowBase = blockIdx.x * 128;

    // per-thread staging slots: idx_k = tid + 128*k  (k=0..4) -> (row, q)
    int rrow[5], rq[5];
#pragma unroll
    for (int k = 0; k < 5; k++) { int idx = tid + 128 * k; rrow[k] = idx / 5; rq[k] = idx % 5; }

    float4 rS[5];
    ull rw0, rw1;

    // preload chunk 0
#pragma unroll
    for (int k = 0; k < 5; k++)
        rS[k] = *reinterpret_cast<const float4*>(S + (size_t)(rowBase + rrow[k]) * K + rq[k] * 4);
    rw0 = Wp[tid];
    rw1 = (tid < 72) ? Wp[tid + 128] : 0ull;

    ull acc[10];
#pragma unroll
    for (int p = 0; p < 10; p++) acc[p] = 0ull;

    for (int c = 0; c < nCh; c++) {
        int buf = c & 1;
        // commit staged registers to smem
#pragma unroll
        for (int k = 0; k < 5; k++) {
            float* dstp = &sS[buf][rrow[k]][rq[k] * 4];
            dstp[0] = rS[k].x; dstp[1] = rS[k].y; dstp[2] = rS[k].z; dstp[3] = rS[k].w;
        }
        sW[buf][tid] = rw0;
        if (tid < 72) sW[buf][tid + 128] = rw1;
        __syncthreads();

        // prefetch next chunk while computing this one
        if (c + 1 < nCh) {
            int off = (c + 1) * 20;
#pragma unroll
            for (int k = 0; k < 5; k++)
                rS[k] = *reinterpret_cast<const float4*>(
                    S + (size_t)(rowBase + rrow[k]) * K + off + rq[k] * 4);
            rw0 = Wp[(c + 1) * 200 + tid];
            if (tid < 72) rw1 = Wp[(c + 1) * 200 + tid + 128];
        }

#pragma unroll
        for (int j = 0; j < 20; j++) {
            float v = sS[buf][tid][j];
            ull vv = pack2(v, v);
#pragma unroll
            for (int p = 0; p < 10; p++) acc[p] = fma2(vv, sW[buf][j * 10 + p], acc[p]);
        }
        __syncthreads();
    }

    int r = rowBase + tid;
    int b = r / T_N;
    int t = r % T_N;
    float* outp = syn + (size_t)b * SUB * T_N + t;
#pragma unroll
    for (int p = 0; p < 10; p++) {
        float h0, h1; unpack2(acc[p], h0, h1);
        outp[(size_t)(2 * p) * T_N] = h0;
        outp[(size_t)(2 * p + 1) * T_N] = h1;
    }
}

// ---------------- kernel 4: 200-tap causal conv (e+i) + tanh + layer2 reduce ----------------
// Block: 256 threads, tile of 1024 t (4 per thread, strided by 256).
// syn values pre-packed (v,v) in smem; taps read as LDS.128.
#define CTILE 1024
#define CHALO 199
#define CSME (CTILE + CHALO)   // 1223

__global__ void __launch_bounds__(256) conv_kernel(float* __restrict__ dout, int out_size)
{
    __shared__ __align__(16) ull sE[CSME];
    __shared__ __align__(16) ull sI[CSME];
    __shared__ __align__(16) ull sK[TNO * 10];
    int tid = threadIdx.x;
    int s = blockIdx.y, b = blockIdx.z;
    int t0 = blockIdx.x * CTILE;

    const float* se = g_syn_e + (size_t)(b * SUB + s) * T_N;
    const float* si = g_syn_i + (size_t)(b * SUB + s) * T_N;
    for (int l = tid; l < CSME; l += 256) {
        int t = t0 - CHALO + l;
        bool ok = (t >= 0 && t < T_N);
        float ve = ok ? se[t] : 0.f;
        float vi = ok ? si[t] : 0.f;
        sE[l] = pack2(ve, ve);
        sI[l] = pack2(vi, vi);
    }
    const ull* Kg = g_Kp + (size_t)s * (TNO * 10);
    for (int l = tid; l < TNO * 10; l += 256) sK[l] = Kg[l];
    __syncthreads();

    float* subdst = (out_size == 1730000) ? (dout + 80000) : g_sub_scratch;
    float ew[10];
#pragma unroll
    for (int h = 0; h < 10; h++) ew[h] = g_expW2[s * 10 + h];

    ull acc[4][5];
#pragma unroll
    for (int j = 0; j < 4; j++)
#pragma unroll
        for (int p = 0; p < 5; p++) acc[j][p] = g_biasP[s * 5 + p];

    int l0 = CHALO + tid;   // entry for (j=0, d=0); t_j entry = l0 + j*256 - d

#pragma unroll 2
    for (int d = 0; d < TNO; d++) {
        const ulonglong2* kp = reinterpret_cast<const ulonglong2*>(&sK[d * 10]);
        ulonglong2 k01 = kp[0], k23 = kp[1], k45 = kp[2], k67 = kp[3], k89 = kp[4];
        ull kk[10] = { k01.x, k01.y, k23.x, k23.y, k45.x, k45.y, k67.x, k67.y, k89.x, k89.y };
#pragma unroll
        for (int j = 0; j < 4; j++) {
            int li = l0 + j * 256 - d;
            ull ve = sE[li];
            ull vi = sI[li];
            acc[j][0] = fma2(ve, kk[0], acc[j][0]);
            acc[j][1] = fma2(ve, kk[1], acc[j][1]);
            acc[j][2] = fma2(ve, kk[2], acc[j][2]);
            acc[j][3] = fma2(ve, kk[3], acc[j][3]);
            acc[j][4] = fma2(ve, kk[4], acc[j][4]);
            acc[j][0] = fma2(vi, kk[5], acc[j][0]);
            acc[j][1] = fma2(vi, kk[6], acc[j][1]);
            acc[j][2] = fma2(vi, kk[7], acc[j][2]);
            acc[j][3] = fma2(vi, kk[8], acc[j][3]);
            acc[j][4] = fma2(vi, kk[9], acc[j][4]);
        }
    }

#pragma unroll
    for (int j = 0; j < 4; j++) {
        int t = t0 + tid + j * 256;
        if (t >= T_N) continue;
        float res = 0.f;
#pragma unroll
        for (int p = 0; p < 5; p++) {
            float h0, h1; unpack2(acc[j][p], h0, h1);
            res += tanhf(h0) * ew[2 * p] + tanhf(h1) * ew[2 * p + 1];
        }
        subdst[((size_t)b * T_N + t) * SUB + s] = res;
    }
}

// ---------------- kernel 5: final[b,t] = sum_s sub_out + V_o ----------------
__global__ void final_kernel(float* dout, int out_size, const float* __restrict__ Vo)
{
    int idx = blockIdx.x * blockDim.x + threadIdx.x;
    if (idx >= B_N * T_N) return;
    const float* src = (out_size == 1730000) ? (dout + 80000) : g_sub_scratch;
    const float4* p = reinterpret_cast<const float4*>(src + (size_t)idx * SUB);
    float sum = 0.f;
#pragma unroll
    for (int i = 0; i < 5; i++) {
        float4 v = p[i];
        sum += v.x + v.y + v.z + v.w;
    }
    dout[idx] = sum + Vo[0];
}

// ---------------- launch ----------------
extern "C" void kernel_launch(void* const* d_in, const int* in_sizes, int n_in,
                              void* d_out, int out_size)
{
    const float* S_e     = (const float*)d_in[0];
    const float* S_i     = (const float*)d_in[1];
    const int*   testp   = (const int*)  d_in[3];
    const float* g_e     = (const float*)d_in[4];
    const float* g_i     = (const float*)d_in[5];
    const float* E_scale = (const float*)d_in[6];
    const float* I_scale = (const float*)d_in[7];
    const float* We      = (const float*)d_in[8];
    const float* Wi      = (const float*)d_in[9];
    const float* W2      = (const float*)d_in[10];
    const float* b1      = (const float*)d_in[11];
    const float* Ce      = (const float*)d_in[12];
    const float* Ci      = (const float*)d_in[13];
    const float* Vo      = (const float*)d_in[14];
    float* out = (float*)d_out;

    softmax_kernel<<<(E_N + 127) / 128, 128>>>(Ce, g_e, E_scale, testp, E_N, 1, out, out_size);
    softmax_kernel<<<(I_N + 127) / 128, 128>>>(Ci, g_i, I_scale, testp, I_N, 0, out, out_size);
    prep_kernel<<<(SUB * TNO * 10 + 255) / 256, 256>>>(We, Wi, W2, b1);
    dim3 gg(625, 2);
    gemm_kernel<<<gg, 128>>>(S_e, S_i);
    dim3 cg((T_N + CTILE - 1) / CTILE, SUB, B_N);
    conv_kernel<<<cg, 256>>>(out, out_size);
    final_kernel<<<(B_N * T_N + 255) / 256, 256>>>(out, out_size, Vo);
}

// round 7
// speedup vs baseline: 1.5406x; 1.1194x over previous
#include <cuda_runtime.h>
#include <cstdint>

#define B_N 4
#define T_N 20000
#define E_N 2000
#define I_N 500
#define SUB 20
#define HID 10
#define COS 24
#define TNO 200

typedef unsigned long long ull;

// ---------------- scratch (static device globals; no allocation) ----------------
__device__ float  g_syn_e[B_N * SUB * T_N];
__device__ float  g_syn_i[B_N * SUB * T_N];
__device__ ull    g_Wpe[E_N * 10];          // packed sub-pair weights (C*exp(scale))
__device__ ull    g_Wpi[I_N * 10];
__device__ ull    g_Kp[SUB * TNO * 10];     // combined conv taps: [s][d][p], p<5 E-pairs, p>=5 I-pairs
__device__ float  g_expW2[SUB * HID];
__device__ ull    g_biasP[SUB * 5];
__device__ float  g_sub_scratch[B_N * T_N * SUB];
__device__ float  g_Ce_scratch[SUB * E_N];
__device__ float  g_Ci_scratch[SUB * I_N];

// ---------------- f32x2 packed-math helpers (sm_103a) ----------------
__device__ __forceinline__ ull pack2(float x, float y) {
    ull r; asm("mov.b64 %0,{%1,%2};" : "=l"(r) : "f"(x), "f"(y)); return r;
}
__device__ __forceinline__ ull fma2(ull a, ull b, ull c) {
    ull d; asm("fma.rn.f32x2 %0,%1,%2,%3;" : "=l"(d) : "l"(a), "l"(b), "l"(c)); return d;
}
__device__ __forceinline__ void unpack2(ull v, float& x, float& y) {
    asm("mov.b64 {%0,%1},%2;" : "=f"(x), "=f"(y) : "l"(v));
}
__device__ __forceinline__ void cpa16(uint32_t smem, const void* gmem) {
    asm volatile("cp.async.cg.shared.global [%0], [%1], 16;" :: "r"(smem), "l"(gmem));
}

// ---------------- kernel 1: column softmax over subs + packed weight build ----------------
__global__ void softmax_kernel(const float* __restrict__ raw, const float* __restrict__ g,
                               const float* __restrict__ lsc, const int* __restrict__ testp,
                               int N, int isE, float* dout, int out_size)
{
    int e = blockIdx.x * blockDim.x + threadIdx.x;
    if (e >= N) return;
    int test = *testp;
    float sc = test ? 10000.f : 1000.f;
    float v[SUB];
    float m = -1e30f;
#pragma unroll
    for (int s = 0; s < SUB; s++) {
        float x = raw[s * N + e];
        if (!test) x += g[s * N + e];
        x *= sc;
        v[s] = x;
        m = fmaxf(m, x);
    }
    float sum = 0.f;
#pragma unroll
    for (int s = 0; s < SUB; s++) { v[s] = expf(v[s] - m); sum += v[s]; }
    float inv = 1.f / sum;
#pragma unroll
    for (int s = 0; s < SUB; s++) v[s] *= inv;

    float* cdst;
    if (out_size == 1730000) cdst = dout + (isE ? 1680000 : 1720000);
    else                     cdst = isE ? g_Ce_scratch : g_Ci_scratch;
#pragma unroll
    for (int s = 0; s < SUB; s++) cdst[s * N + e] = v[s];

    float ex = expf(lsc[e]);
    ull* wp = isE ? g_Wpe : g_Wpi;
#pragma unroll
    for (int p = 0; p < 10; p++)
        wp[e * 10 + p] = pack2(v[2 * p] * ex, v[2 * p + 1] * ex);
}

// ---------------- kernel 2: fold basis into combined 200-tap conv kernels ----------------
__device__ __forceinline__ float basisv(int k, int d) {
    const float PI = 3.14159265358979f;
    float raw = 6.f * logf((float)d + 1.f + 1e-7f);
    float phi = 1.57079632679f * (float)k;
    if (raw >= phi - PI && raw <= phi + PI) return 0.5f * cosf(raw - phi) + 0.5f;
    return 0.f;
}

__global__ void prep_kernel(const float* __restrict__ We, const float* __restrict__ Wi,
                            const float* __restrict__ W2, const float* __restrict__ b1)
{
    int i = blockIdx.x * blockDim.x + threadIdx.x;
    if (i < SUB * HID) g_expW2[i] = expf(W2[i]);
    if (i < SUB * 5)   g_biasP[i] = pack2(b1[2 * i], b1[2 * i + 1]);
    if (i >= SUB * TNO * 10) return;
    int s = i / (TNO * 10);
    int r = i % (TNO * 10);
    int d = r / 10;
    int p = r % 10;
    const float* W = (p < 5) ? We : Wi;
    int pp = (p < 5) ? p : (p - 5);
    float k0 = 0.f, k1 = 0.f;
#pragma unroll
    for (int k = 0; k < COS; k++) {
        float bv = basisv(k, d);
        k0 += bv * W[(s * HID + 2 * pp) * COS + k];
        k1 += bv * W[(s * HID + 2 * pp + 1) * COS + k];
    }
    g_Kp[(s * TNO + d) * 10 + p] = pack2(k0, k1);
}

// ---------------- kernel 3: syn = S @ W^T  merged E/I, 3-stage cp.async pipeline ----------------
// S tile per stage: 128 rows x 20 floats at row stride 80B (no padding needed:
// LDS.128 column reads at float4-stride 5 hit all 32 banks per 8-lane phase).
#define GSTG 3

__global__ void __launch_bounds__(128, 6) gemm_kernel(const float* __restrict__ SE,
                                                      const float* __restrict__ SI)
{
    __shared__ __align__(16) float sS[GSTG][128 * 20];
    __shared__ __align__(16) ull   sW[GSTG][200];
    int isE = (blockIdx.y == 0);
    const float* S  = isE ? SE : SI;
    int K           = isE ? E_N : I_N;
    int nCh         = K / 20;
    const ull* Wp   = isE ? g_Wpe : g_Wpi;
    float* syn      = isE ? g_syn_e : g_syn_i;

    int tid = threadIdx.x;
    size_t rowBase = (size_t)blockIdx.x * 128;
    const float* Sbase = S + rowBase * K;

    ull acc[10];
#pragma unroll
    for (int p = 0; p < 10; p++) acc[p] = 0ull;

    // issue stage for chunk c into buffer c%3
    auto issue = [&](int c) {
        int buf = c % GSTG;
        uint32_t sSb = (uint32_t)__cvta_generic_to_shared(&sS[buf][0]);
        uint32_t sWb = (uint32_t)__cvta_generic_to_shared(&sW[buf][0]);
#pragma unroll
        for (int k = 0; k < 5; k++) {
            int idx = tid + 128 * k;
            int row = idx / 5, q = idx - row * 5;
            cpa16(sSb + row * 80 + q * 16, Sbase + (size_t)row * K + c * 20 + q * 4);
        }
        if (tid < 100)
            cpa16(sWb + tid * 16, Wp + c * 200 + tid * 2);
    };

    issue(0); asm volatile("cp.async.commit_group;");
    issue(1); asm volatile("cp.async.commit_group;");
    issue(2); asm volatile("cp.async.commit_group;");

    for (int c = 0; c < nCh; c++) {
        asm volatile("cp.async.wait_group 2;");
        __syncthreads();
        int buf = c % GSTG;
        const float4* vrow = reinterpret_cast<const float4*>(&sS[buf][tid * 20]);
        const ull* wb = &sW[buf][0];
#pragma unroll
        for (int jq = 0; jq < 5; jq++) {
            float4 v4 = vrow[jq];
            float va[4] = { v4.x, v4.y, v4.z, v4.w };
#pragma unroll
            for (int i = 0; i < 4; i++) {
                ull vv = pack2(va[i], va[i]);
                const ulonglong2* wp2 =
                    reinterpret_cast<const ulonglong2*>(wb + (jq * 4 + i) * 10);
                ulonglong2 w0 = wp2[0], w1 = wp2[1], w2 = wp2[2], w3 = wp2[3], w4 = wp2[4];
                acc[0] = fma2(vv, w0.x, acc[0]);
                acc[1] = fma2(vv, w0.y, acc[1]);
                acc[2] = fma2(vv, w1.x, acc[2]);
                acc[3] = fma2(vv, w1.y, acc[3]);
                acc[4] = fma2(vv, w2.x, acc[4]);
                acc[5] = fma2(vv, w2.y, acc[5]);
                acc[6] = fma2(vv, w3.x, acc[6]);
                acc[7] = fma2(vv, w3.y, acc[7]);
                acc[8] = fma2(vv, w4.x, acc[8]);
                acc[9] = fma2(vv, w4.y, acc[9]);
            }
        }
        __syncthreads();
        if (c + GSTG < nCh) issue(c + GSTG);
        asm volatile("cp.async.commit_group;");
    }

    size_t r = rowBase + tid;
    int b = (int)(r / T_N);
    int t = (int)(r % T_N);
    float* outp = syn + (size_t)b * SUB * T_N + t;
#pragma unroll
    for (int p = 0; p < 10; p++) {
        float h0, h1; unpack2(acc[p], h0, h1);
        outp[(size_t)(2 * p) * T_N] = h0;
        outp[(size_t)(2 * p + 1) * T_N] = h1;
    }
}

// ---------------- kernel 4: 200-tap causal conv (e+i) + tanh + layer2 reduce ----------------
// Block: 256 threads, tile of 1024 t (4 per thread, strided by 256).
// syn values pre-packed (v,v) in smem; taps read as LDS.128.
#define CTILE 1024
#define CHALO 199
#define CSME (CTILE + CHALO)   // 1223

__global__ void __launch_bounds__(256, 3) conv_kernel(float* __restrict__ dout, int out_size)
{
    __shared__ __align__(16) ull sE[CSME];
    __shared__ __align__(16) ull sI[CSME];
    __shared__ __align__(16) ull sK[TNO * 10];
    int tid = threadIdx.x;
    int s = blockIdx.y, b = blockIdx.z;
    int t0 = blockIdx.x * CTILE;

    const float* se = g_syn_e + (size_t)(b * SUB + s) * T_N;
    const float* si = g_syn_i + (size_t)(b * SUB + s) * T_N;
    for (int l = tid; l < CSME; l += 256) {
        int t = t0 - CHALO + l;
        bool ok = (t >= 0 && t < T_N);
        float ve = ok ? se[t] : 0.f;
        float vi = ok ? si[t] : 0.f;
        sE[l] = pack2(ve, ve);
        sI[l] = pack2(vi, vi);
    }
    const ull* Kg = g_Kp + (size_t)s * (TNO * 10);
    for (int l = tid; l < TNO * 10; l += 256) sK[l] = Kg[l];
    __syncthreads();

    ull acc[4][5];
#pragma unroll
    for (int j = 0; j < 4; j++)
#pragma unroll
        for (int p = 0; p < 5; p++) acc[j][p] = g_biasP[s * 5 + p];

    int l0 = CHALO + tid;   // entry for (j=0, d=0); t_j entry = l0 + j*256 - d

#pragma unroll 2
    for (int d = 0; d < TNO; d++) {
        const ulonglong2* kp = reinterpret_cast<const ulonglong2*>(&sK[d * 10]);
        ulonglong2 k01 = kp[0], k23 = kp[1], k45 = kp[2], k67 = kp[3], k89 = kp[4];
#pragma unroll
        for (int j = 0; j < 4; j++) {
            int li = l0 + j * 256 - d;
            ull ve = sE[li];
            ull vi = sI[li];
            acc[j][0] = fma2(ve, k01.x, acc[j][0]);
            acc[j][1] = fma2(ve, k01.y, acc[j][1]);
            acc[j][2] = fma2(ve, k23.x, acc[j][2]);
            acc[j][3] = fma2(ve, k23.y, acc[j][3]);
            acc[j][4] = fma2(ve, k45.x, acc[j][4]);
            acc[j][0] = fma2(vi, k45.y, acc[j][0]);
            acc[j][1] = fma2(vi, k67.x, acc[j][1]);
            acc[j][2] = fma2(vi, k67.y, acc[j][2]);
            acc[j][3] = fma2(vi, k89.x, acc[j][3]);
            acc[j][4] = fma2(vi, k89.y, acc[j][4]);
        }
    }

    float* subdst = (out_size == 1730000) ? (dout + 80000) : g_sub_scratch;
    float ew[10];
#pragma unroll
    for (int h = 0; h < 10; h++) ew[h] = g_expW2[s * 10 + h];

#pragma unroll
    for (int j = 0; j < 4; j++) {
        int t = t0 + tid + j * 256;
        if (t >= T_N) continue;
        float res = 0.f;
#pragma unroll
        for (int p = 0; p < 5; p++) {
            float h0, h1; unpack2(acc[j][p], h0, h1);
            res += tanhf(h0) * ew[2 * p] + tanhf(h1) * ew[2 * p + 1];
        }
        subdst[((size_t)b * T_N + t) * SUB + s] = res;
    }
}

// ---------------- kernel 5: final[b,t] = sum_s sub_out + V_o ----------------
__global__ void final_kernel(float* dout, int out_size, const float* __restrict__ Vo)
{
    int idx = blockIdx.x * blockDim.x + threadIdx.x;
    if (idx >= B_N * T_N) return;
    const float* src = (out_size == 1730000) ? (dout + 80000) : g_sub_scratch;
    const float4* p = reinterpret_cast<const float4*>(src + (size_t)idx * SUB);
    float sum = 0.f;
#pragma unroll
    for (int i = 0; i < 5; i++) {
        float4 v = p[i];
        sum += v.x + v.y + v.z + v.w;
    }
    dout[idx] = sum + Vo[0];
}

// ---------------- launch ----------------
extern "C" void kernel_launch(void* const* d_in, const int* in_sizes, int n_in,
                              void* d_out, int out_size)
{
    const float* S_e     = (const float*)d_in[0];
    const float* S_i     = (const float*)d_in[1];
    const int*   testp   = (const int*)  d_in[3];
    const float* g_e     = (const float*)d_in[4];
    const float* g_i     = (const float*)d_in[5];
    const float* E_scale = (const float*)d_in[6];
    const float* I_scale = (const float*)d_in[7];
    const float* We      = (const float*)d_in[8];
    const float* Wi      = (const float*)d_in[9];
    const float* W2      = (const float*)d_in[10];
    const float* b1      = (const float*)d_in[11];
    const float* Ce      = (const float*)d_in[12];
    const float* Ci      = (const float*)d_in[13];
    const float* Vo      = (const float*)d_in[14];
    float* out = (float*)d_out;

    softmax_kernel<<<(E_N + 127) / 128, 128>>>(Ce, g_e, E_scale, testp, E_N, 1, out, out_size);
    softmax_kernel<<<(I_N + 127) / 128, 128>>>(Ci, g_i, I_scale, testp, I_N, 0, out, out_size);
    prep_kernel<<<(SUB * TNO * 10 + 255) / 256, 256>>>(We, Wi, W2, b1);
    dim3 gg(625, 2);
    gemm_kernel<<<gg, 128>>>(S_e, S_i);
    dim3 cg((T_N + CTILE - 1) / CTILE, SUB, B_N);
    conv_kernel<<<cg, 256>>>(out, out_size);
    final_kernel<<<(B_N * T_N + 255) / 256, 256>>>(out, out_size, Vo);
}

// round 10
// speedup vs baseline: 1.6206x; 1.0519x over previous
#include <cuda_runtime.h>
#include <cstdint>

#define B_N 4
#define T_N 20000
#define E_N 2000
#define I_N 500
#define SUB 20
#define HID 10
#define COS 24
#define TNO 200

typedef unsigned long long ull;

// ---------------- scratch (static device globals; no allocation) ----------------
__device__ float  g_syn_e[B_N * SUB * T_N];
__device__ float  g_syn_i[B_N * SUB * T_N];
__device__ ull    g_Wpe[E_N * 10];          // packed sub-pair weights (C*exp(scale))
__device__ ull    g_Wpi[I_N * 10];
__device__ ull    g_Kp[SUB * TNO * 10];     // combined conv taps: [s][d][p], p<5 E-pairs, p>=5 I-pairs
__device__ float  g_expW2[SUB * HID];
__device__ ull    g_biasP[SUB * 5];
__device__ float  g_sub_scratch[B_N * T_N * SUB];
__device__ float  g_Ce_scratch[SUB * E_N];
__device__ float  g_Ci_scratch[SUB * I_N];

// ---------------- f32x2 packed-math helpers (sm_103a) ----------------
__device__ __forceinline__ ull pack2(float x, float y) {
    ull r; asm("mov.b64 %0,{%1,%2};" : "=l"(r) : "f"(x), "f"(y)); return r;
}
__device__ __forceinline__ ull fma2(ull a, ull b, ull c) {
    ull d; asm("fma.rn.f32x2 %0,%1,%2,%3;" : "=l"(d) : "l"(a), "l"(b), "l"(c)); return d;
}
__device__ __forceinline__ void unpack2(ull v, float& x, float& y) {
    asm("mov.b64 {%0,%1},%2;" : "=f"(x), "=f"(y) : "l"(v));
}
__device__ __forceinline__ void cpa16(uint32_t smem, const void* gmem) {
    asm volatile("cp.async.cg.shared.global [%0], [%1], 16;" :: "r"(smem), "l"(gmem));
}

// ---------------- kernel 1: column softmax over subs + packed weight build ----------------
__global__ void softmax_kernel(const float* __restrict__ raw, const float* __restrict__ g,
                               const float* __restrict__ lsc, const int* __restrict__ testp,
                               int N, int isE, float* dout, int out_size)
{
    int e = blockIdx.x * blockDim.x + threadIdx.x;
    if (e >= N) return;
    int test = *testp;
    float sc = test ? 10000.f : 1000.f;
    float v[SUB];
    float m = -1e30f;
#pragma unroll
    for (int s = 0; s < SUB; s++) {
        float x = raw[s * N + e];
        if (!test) x += g[s * N + e];
        x *= sc;
        v[s] = x;
        m = fmaxf(m, x);
    }
    float sum = 0.f;
#pragma unroll
    for (int s = 0; s < SUB; s++) { v[s] = expf(v[s] - m); sum += v[s]; }
    float inv = 1.f / sum;
#pragma unroll
    for (int s = 0; s < SUB; s++) v[s] *= inv;

    float* cdst;
    if (out_size == 1730000) cdst = dout + (isE ? 1680000 : 1720000);
    else                     cdst = isE ? g_Ce_scratch : g_Ci_scratch;
#pragma unroll
    for (int s = 0; s < SUB; s++) cdst[s * N + e] = v[s];

    float ex = expf(lsc[e]);
    ull* wp = isE ? g_Wpe : g_Wpi;
#pragma unroll
    for (int p = 0; p < 10; p++)
        wp[e * 10 + p] = pack2(v[2 * p] * ex, v[2 * p + 1] * ex);
}

// ---------------- kernel 2: fold basis into combined 200-tap conv kernels ----------------
__device__ __forceinline__ float basisv(int k, int d) {
    const float PI = 3.14159265358979f;
    float raw = 6.f * logf((float)d + 1.f + 1e-7f);
    float phi = 1.57079632679f * (float)k;
    if (raw >= phi - PI && raw <= phi + PI) return 0.5f * cosf(raw - phi) + 0.5f;
    return 0.f;
}

__global__ void prep_kernel(const float* __restrict__ We, const float* __restrict__ Wi,
                            const float* __restrict__ W2, const float* __restrict__ b1)
{
    int i = blockIdx.x * blockDim.x + threadIdx.x;
    if (i < SUB * HID) g_expW2[i] = expf(W2[i]);
    if (i < SUB * 5)   g_biasP[i] = pack2(b1[2 * i], b1[2 * i + 1]);
    if (i >= SUB * TNO * 10) return;
    int s = i / (TNO * 10);
    int r = i % (TNO * 10);
    int d = r / 10;
    int p = r % 10;
    const float* W = (p < 5) ? We : Wi;
    int pp = (p < 5) ? p : (p - 5);
    float k0 = 0.f, k1 = 0.f;
#pragma unroll
    for (int k = 0; k < COS; k++) {
        float bv = basisv(k, d);
        k0 += bv * W[(s * HID + 2 * pp) * COS + k];
        k1 += bv * W[(s * HID + 2 * pp + 1) * COS + k];
    }
    g_Kp[(s * TNO + d) * 10 + p] = pack2(k0, k1);
}

// ---------------- kernel 3: syn = S @ W^T  merged E/I, M-tile=2, 2-stage cp.async ----------------
// 256 rows/CTA, 128 threads: thread owns rows (tid) and (tid+128). The 100
// broadcast W LDS.128 per chunk now feed 400 fma2 (2 rows), doubling ILP.
#define GROWS 256
#define NROW_TOT (B_N * T_N)

__global__ void __launch_bounds__(128, 5) gemm_kernel(const float* __restrict__ SE,
                                                      const float* __restrict__ SI)
{
    __shared__ __align__(16) float sS[2][GROWS * 20];
    __shared__ __align__(16) ull   sW[2][200];
    int isE = (blockIdx.y == 0);
    const float* S  = isE ? SE : SI;
    int K           = isE ? E_N : I_N;
    int nCh         = K / 20;
    const ull* Wp   = isE ? g_Wpe : g_Wpi;
    float* syn      = isE ? g_syn_e : g_syn_i;

    int tid = threadIdx.x;
    size_t rowBase = (size_t)blockIdx.x * GROWS;

    // issue stage for chunk c into buffer c&1 (10 S-loads + up to 1 W-load per thread)
    auto issue = [&](int c) {
        int buf = c & 1;
        uint32_t sSb = (uint32_t)__cvta_generic_to_shared(&sS[buf][0]);
        uint32_t sWb = (uint32_t)__cvta_generic_to_shared(&sW[buf][0]);
#pragma unroll
        for (int k = 0; k < 10; k++) {
            int idx = tid + 128 * k;
            int row = idx / 5, q = idx - row * 5;
            size_t rowg = rowBase + row;
            if (rowg > NROW_TOT - 1) rowg = NROW_TOT - 1;   // tail clamp (dup read, unstored)
            cpa16(sSb + row * 80 + q * 16, S + rowg * K + c * 20 + q * 4);
        }
        if (tid < 100)
            cpa16(sWb + tid * 16, Wp + c * 200 + tid * 2);
    };

    issue(0); asm volatile("cp.async.commit_group;");
    issue(1); asm volatile("cp.async.commit_group;");

    ull acc0[10], acc1[10];
#pragma unroll
    for (int p = 0; p < 10; p++) { acc0[p] = 0ull; acc1[p] = 0ull; }

    for (int c = 0; c < nCh; c++) {
        asm volatile("cp.async.wait_group 1;");
        __syncthreads();
        int buf = c & 1;
        const float4* vr0 = reinterpret_cast<const float4*>(&sS[buf][tid * 20]);
        const float4* vr1 = reinterpret_cast<const float4*>(&sS[buf][(tid + 128) * 20]);
        const ull* wb = &sW[buf][0];
#pragma unroll
        for (int jq = 0; jq < 5; jq++) {
            float4 a4 = vr0[jq];
            float4 b4 = vr1[jq];
            float aa[4] = { a4.x, a4.y, a4.z, a4.w };
            float bb[4] = { b4.x, b4.y, b4.z, b4.w };
#pragma unroll
            for (int i = 0; i < 4; i++) {
                ull va = pack2(aa[i], aa[i]);
                ull vb = pack2(bb[i], bb[i]);
                const ulonglong2* wp2 =
                    reinterpret_cast<const ulonglong2*>(wb + (jq * 4 + i) * 10);
                ulonglong2 w0 = wp2[0], w1 = wp2[1], w2 = wp2[2], w3 = wp2[3], w4 = wp2[4];
                acc0[0] = fma2(va, w0.x, acc0[0]);  acc1[0] = fma2(vb, w0.x, acc1[0]);
                acc0[1] = fma2(va, w0.y, acc0[1]);  acc1[1] = fma2(vb, w0.y, acc1[1]);
                acc0[2] = fma2(va, w1.x, acc0[2]);  acc1[2] = fma2(vb, w1.x, acc1[2]);
                acc0[3] = fma2(va, w1.y, acc0[3]);  acc1[3] = fma2(vb, w1.y, acc1[3]);
                acc0[4] = fma2(va, w2.x, acc0[4]);  acc1[4] = fma2(vb, w2.x, acc1[4]);
                acc0[5] = fma2(va, w2.y, acc0[5]);  acc1[5] = fma2(vb, w2.y, acc1[5]);
                acc0[6] = fma2(va, w3.x, acc0[6]);  acc1[6] = fma2(vb, w3.x, acc1[6]);
                acc0[7] = fma2(va, w3.y, acc0[7]);  acc1[7] = fma2(vb, w3.y, acc1[7]);
                acc0[8] = fma2(va, w4.x, acc0[8]);  acc1[8] = fma2(vb, w4.x, acc1[8]);
                acc0[9] = fma2(va, w4.y, acc0[9]);  acc1[9] = fma2(vb, w4.y, acc1[9]);
            }
        }
        __syncthreads();
        if (c + 2 < nCh) issue(c + 2);
        asm volatile("cp.async.commit_group;");
    }

    // epilogue: store both rows (guard tail)
#pragma unroll
    for (int half = 0; half < 2; half++) {
        size_t r = rowBase + tid + half * 128;
        if (r >= NROW_TOT) break;
        ull* accp = half ? acc1 : acc0;
        int b = (int)(r / T_N);
        int t = (int)(r % T_N);
        float* outp = syn + (size_t)b * SUB * T_N + t;
#pragma unroll
        for (int p = 0; p < 10; p++) {
            float h0, h1; unpack2(accp[p], h0, h1);
            outp[(size_t)(2 * p) * T_N] = h0;
            outp[(size_t)(2 * p + 1) * T_N] = h1;
        }
    }
}

// ---------------- kernel 4: 200-tap causal conv (e+i) + tanh + layer2 reduce ----------------
// Block: 256 threads, tile of 1024 t (4 per thread, strided by 256).
// syn values pre-packed (v,v) in smem; taps read as LDS.128.
#define CTILE 1024
#define CHALO 199
#define CSME (CTILE + CHALO)   // 1223

__global__ void __launch_bounds__(256, 3) conv_kernel(float* __restrict__ dout, int out_size)
{
    __shared__ __align__(16) ull sE[CSME];
    __shared__ __align__(16) ull sI[CSME];
    __shared__ __align__(16) ull sK[TNO * 10];
    int tid = threadIdx.x;
    int s = blockIdx.y, b = blockIdx.z;
    int t0 = blockIdx.x * CTILE;

    const float* se = g_syn_e + (size_t)(b * SUB + s) * T_N;
    const float* si = g_syn_i + (size_t)(b * SUB + s) * T_N;
    for (int l = tid; l < CSME; l += 256) {
        int t = t0 - CHALO + l;
        bool ok = (t >= 0 && t < T_N);
        float ve = ok ? se[t] : 0.f;
        float vi = ok ? si[t] : 0.f;
        sE[l] = pack2(ve, ve);
        sI[l] = pack2(vi, vi);
    }
    const ull* Kg = g_Kp + (size_t)s * (TNO * 10);
    for (int l = tid; l < TNO * 10; l += 256) sK[l] = Kg[l];
    __syncthreads();

    ull acc[4][5];
#pragma unroll
    for (int j = 0; j < 4; j++)
#pragma unroll
        for (int p = 0; p < 5; p++) acc[j][p] = g_biasP[s * 5 + p];

    int l0 = CHALO + tid;   // entry for (j=0, d=0); t_j entry = l0 + j*256 - d

#pragma unroll 2
    for (int d = 0; d < TNO; d++) {
        const ulonglong2* kp = reinterpret_cast<const ulonglong2*>(&sK[d * 10]);
        ulonglong2 k01 = kp[0], k23 = kp[1], k45 = kp[2], k67 = kp[3], k89 = kp[4];
#pragma unroll
        for (int j = 0; j < 4; j++) {
            int li = l0 + j * 256 - d;
            ull ve = sE[li];
            ull vi = sI[li];
            acc[j][0] = fma2(ve, k01.x, acc[j][0]);
            acc[j][1] = fma2(ve, k01.y, acc[j][1]);
            acc[j][2] = fma2(ve, k23.x, acc[j][2]);
            acc[j][3] = fma2(ve, k23.y, acc[j][3]);
            acc[j][4] = fma2(ve, k45.x, acc[j][4]);
            acc[j][0] = fma2(vi, k45.y, acc[j][0]);
            acc[j][1] = fma2(vi, k67.x, acc[j][1]);
            acc[j][2] = fma2(vi, k67.y, acc[j][2]);
            acc[j][3] = fma2(vi, k89.x, acc[j][3]);
            acc[j][4] = fma2(vi, k89.y, acc[j][4]);
        }
    }

    float* subdst = (out_size == 1730000) ? (dout + 80000) : g_sub_scratch;
    float ew[10];
#pragma unroll
    for (int h = 0; h < 10; h++) ew[h] = g_expW2[s * 10 + h];

#pragma unroll
    for (int j = 0; j < 4; j++) {
        int t = t0 + tid + j * 256;
        if (t >= T_N) continue;
        float res = 0.f;
#pragma unroll
        for (int p = 0; p < 5; p++) {
            float h0, h1; unpack2(acc[j][p], h0, h1);
            res += tanhf(h0) * ew[2 * p] + tanhf(h1) * ew[2 * p + 1];
        }
        subdst[((size_t)b * T_N + t) * SUB + s] = res;
    }
}

// ---------------- kernel 5: final[b,t] = sum_s sub_out + V_o ----------------
__global__ void final_kernel(float* dout, int out_size, const float* __restrict__ Vo)
{
    int idx = blockIdx.x * blockDim.x + threadIdx.x;
    if (idx >= B_N * T_N) return;
    const float* src = (out_size == 1730000) ? (dout + 80000) : g_sub_scratch;
    const float4* p = reinterpret_cast<const float4*>(src + (size_t)idx * SUB);
    float sum = 0.f;
#pragma unroll
    for (int i = 0; i < 5; i++) {
        float4 v = p[i];
        sum += v.x + v.y + v.z + v.w;
    }
    dout[idx] = sum + Vo[0];
}

// ---------------- launch ----------------
extern "C" void kernel_launch(void* const* d_in, const int* in_sizes, int n_in,
                              void* d_out, int out_size)
{
    const float* S_e     = (const float*)d_in[0];
    const float* S_i     = (const float*)d_in[1];
    const int*   testp   = (const int*)  d_in[3];
    const float* g_e     = (const float*)d_in[4];
    const float* g_i     = (const float*)d_in[5];
    const float* E_scale = (const float*)d_in[6];
    const float* I_scale = (const float*)d_in[7];
    const float* We      = (const float*)d_in[8];
    const float* Wi      = (const float*)d_in[9];
    const float* W2      = (const float*)d_in[10];
    const float* b1      = (const float*)d_in[11];
    const float* Ce      = (const float*)d_in[12];
    const float* Ci      = (const float*)d_in[13];
    const float* Vo      = (const float*)d_in[14];
    float* out = (float*)d_out;

    softmax_kernel<<<(E_N + 127) / 128, 128>>>(Ce, g_e, E_scale, testp, E_N, 1, out, out_size);
    softmax_kernel<<<(I_N + 127) / 128, 128>>>(Ci, g_i, I_scale, testp, I_N, 0, out, out_size);
    prep_kernel<<<(SUB * TNO * 10 + 255) / 256, 256>>>(We, Wi, W2, b1);
    dim3 gg((NROW_TOT + GROWS - 1) / GROWS, 2);
    gemm_kernel<<<gg, 128>>>(S_e, S_i);
    dim3 cg((T_N + CTILE - 1) / CTILE, SUB, B_N);
    conv_kernel<<<cg, 256>>>(out, out_size);
    final_kernel<<<(B_N * T_N + 255) / 256, 256>>>(out, out_size, Vo);
}

// round 14
// speedup vs baseline: 1.8054x; 1.1141x over previous
#include <cuda_runtime.h>
#include <cstdint>

#define B_N 4
#define T_N 20000
#define E_N 2000
#define I_N 500
#define SUB 20
#define HID 10
#define COS 24
#define TNO 200

typedef unsigned long long ull;

// ---------------- scratch (static device globals; no allocation) ----------------
__device__ float  g_syn_ep[3][B_N * SUB * T_N];  // K-split partial E results
__device__ float  g_syn_i[B_N * SUB * T_N];
__device__ ull    g_Wpe[E_N * 10];          // packed sub-pair weights (C*exp(scale))
__device__ ull    g_Wpi[I_N * 10];
__device__ ull    g_Kp[SUB * TNO * 10];     // combined conv taps: [s][d][p], p<5 E-pairs, p>=5 I-pairs
__device__ float  g_expW2[SUB * HID];
__device__ ull    g_biasP[SUB * 5];
__device__ float  g_sub_scratch[B_N * T_N * SUB];
__device__ float  g_Ce_scratch[SUB * E_N];
__device__ float  g_Ci_scratch[SUB * I_N];

// ---------------- f32x2 packed-math helpers (sm_103a) ----------------
__device__ __forceinline__ ull pack2(float x, float y) {
    ull r; asm("mov.b64 %0,{%1,%2};" : "=l"(r) : "f"(x), "f"(y)); return r;
}
__device__ __forceinline__ ull fma2(ull a, ull b, ull c) {
    ull d; asm("fma.rn.f32x2 %0,%1,%2,%3;" : "=l"(d) : "l"(a), "l"(b), "l"(c)); return d;
}
__device__ __forceinline__ void unpack2(ull v, float& x, float& y) {
    asm("mov.b64 {%0,%1},%2;" : "=f"(x), "=f"(y) : "l"(v));
}
__device__ __forceinline__ void cpa16(uint32_t smem, const void* gmem) {
    asm volatile("cp.async.cg.shared.global [%0], [%1], 16;" :: "r"(smem), "l"(gmem));
}

// ---------------- kernel 1: column softmax over subs + packed weight build ----------------
__global__ void softmax_kernel(const float* __restrict__ raw, const float* __restrict__ g,
                               const float* __restrict__ lsc, const int* __restrict__ testp,
                               int N, int isE, float* dout, int out_size)
{
    int e = blockIdx.x * blockDim.x + threadIdx.x;
    if (e >= N) return;
    int test = *testp;
    float sc = test ? 10000.f : 1000.f;
    float v[SUB];
    float m = -1e30f;
#pragma unroll
    for (int s = 0; s < SUB; s++) {
        float x = raw[s * N + e];
        if (!test) x += g[s * N + e];
        x *= sc;
        v[s] = x;
        m = fmaxf(m, x);
    }
    float sum = 0.f;
#pragma unroll
    for (int s = 0; s < SUB; s++) { v[s] = expf(v[s] - m); sum += v[s]; }
    float inv = 1.f / sum;
#pragma unroll
    for (int s = 0; s < SUB; s++) v[s] *= inv;

    float* cdst;
    if (out_size == 1730000) cdst = dout + (isE ? 1680000 : 1720000);
    else                     cdst = isE ? g_Ce_scratch : g_Ci_scratch;
#pragma unroll
    for (int s = 0; s < SUB; s++) cdst[s * N + e] = v[s];

    float ex = expf(lsc[e]);
    ull* wp = isE ? g_Wpe : g_Wpi;
#pragma unroll
    for (int p = 0; p < 10; p++)
        wp[e * 10 + p] = pack2(v[2 * p] * ex, v[2 * p + 1] * ex);
}

// ---------------- kernel 2: fold basis into combined 200-tap conv kernels ----------------
__device__ __forceinline__ float basisv(int k, int d) {
    const float PI = 3.14159265358979f;
    float raw = 6.f * logf((float)d + 1.f + 1e-7f);
    float phi = 1.57079632679f * (float)k;
    if (raw >= phi - PI && raw <= phi + PI) return 0.5f * cosf(raw - phi) + 0.5f;
    return 0.f;
}

__global__ void prep_kernel(const float* __restrict__ We, const float* __restrict__ Wi,
                            const float* __restrict__ W2, const float* __restrict__ b1)
{
    int i = blockIdx.x * blockDim.x + threadIdx.x;
    if (i < SUB * HID) g_expW2[i] = expf(W2[i]);
    if (i < SUB * 5)   g_biasP[i] = pack2(b1[2 * i], b1[2 * i + 1]);
    if (i >= SUB * TNO * 10) return;
    int s = i / (TNO * 10);
    int r = i % (TNO * 10);
    int d = r / 10;
    int p = r % 10;
    const float* W = (p < 5) ? We : Wi;
    int pp = (p < 5) ? p : (p - 5);
    float k0 = 0.f, k1 = 0.f;
#pragma unroll
    for (int k = 0; k < COS; k++) {
        float bv = basisv(k, d);
        k0 += bv * W[(s * HID + 2 * pp) * COS + k];
        k1 += bv * W[(s * HID + 2 * pp + 1) * COS + k];
    }
    g_Kp[(s * TNO + d) * 10 + p] = pack2(k0, k1);
}

// ---------------- kernel 3: syn = S @ W^T  K-split E (3 segs) + I, M-tile=2, 2-stage ----------------
// grid = (313, 4): seg 0..2 = E chunk ranges [0,34) [34,67) [67,100); seg 3 = I [0,25).
// 256 rows/CTA, 128 threads: thread owns rows tid and tid+128.
#define GROWS 256
#define NROW_TOT (B_N * T_N)

__global__ void __launch_bounds__(128, 5) gemm_kernel(const float* __restrict__ SE,
                                                      const float* __restrict__ SI)
{
    __shared__ __align__(16) float sS[2][GROWS * 20];
    __shared__ __align__(16) ull   sW[2][200];
    int seg = blockIdx.y;
    const float* S;
    const ull* Wp;
    float* syn;
    int K, c0, c1;
    if (seg < 3) {
        S = SE; K = E_N; Wp = g_Wpe; syn = g_syn_ep[seg];
        c0 = (seg == 0) ? 0 : (seg == 1 ? 34 : 67);
        c1 = (seg == 0) ? 34 : (seg == 1 ? 67 : 100);
    } else {
        S = SI; K = I_N; Wp = g_Wpi; syn = g_syn_i;
        c0 = 0; c1 = 25;
    }

    int tid = threadIdx.x;
    size_t rowBase = (size_t)blockIdx.x * GROWS;

    // issue stage for absolute chunk c into buffer (c-c0)&1
    auto issue = [&](int c) {
        int buf = (c - c0) & 1;
        uint32_t sSb = (uint32_t)__cvta_generic_to_shared(&sS[buf][0]);
        uint32_t sWb = (uint32_t)__cvta_generic_to_shared(&sW[buf][0]);
#pragma unroll
        for (int k = 0; k < 10; k++) {
            int idx = tid + 128 * k;
            int row = idx / 5, q = idx - row * 5;
            size_t rowg = rowBase + row;
            if (rowg > NROW_TOT - 1) rowg = NROW_TOT - 1;   // tail clamp (dup read, unstored)
            cpa16(sSb + row * 80 + q * 16, S + rowg * K + c * 20 + q * 4);
        }
        if (tid < 100)
            cpa16(sWb + tid * 16, Wp + c * 200 + tid * 2);
    };

    issue(c0);     asm volatile("cp.async.commit_group;");
    issue(c0 + 1); asm volatile("cp.async.commit_group;");

    ull acc0[10], acc1[10];
#pragma unroll
    for (int p = 0; p < 10; p++) { acc0[p] = 0ull; acc1[p] = 0ull; }

    for (int c = c0; c < c1; c++) {
        asm volatile("cp.async.wait_group 1;");
        __syncthreads();
        int buf = (c - c0) & 1;
        const float4* vr0 = reinterpret_cast<const float4*>(&sS[buf][tid * 20]);
        const float4* vr1 = reinterpret_cast<const float4*>(&sS[buf][(tid + 128) * 20]);
        const ull* wb = &sW[buf][0];
#pragma unroll
        for (int jq = 0; jq < 5; jq++) {
            float4 a4 = vr0[jq];
            float4 b4 = vr1[jq];
            float aa[4] = { a4.x, a4.y, a4.z, a4.w };
            float bb[4] = { b4.x, b4.y, b4.z, b4.w };
#pragma unroll
            for (int i = 0; i < 4; i++) {
                ull va = pack2(aa[i], aa[i]);
                ull vb = pack2(bb[i], bb[i]);
                const ulonglong2* wp2 =
                    reinterpret_cast<const ulonglong2*>(wb + (jq * 4 + i) * 10);
                ulonglong2 w0 = wp2[0], w1 = wp2[1], w2 = wp2[2], w3 = wp2[3], w4 = wp2[4];
                acc0[0] = fma2(va, w0.x, acc0[0]);  acc1[0] = fma2(vb, w0.x, acc1[0]);
                acc0[1] = fma2(va, w0.y, acc0[1]);  acc1[1] = fma2(vb, w0.y, acc1[1]);
                acc0[2] = fma2(va, w1.x, acc0[2]);  acc1[2] = fma2(vb, w1.x, acc1[2]);
                acc0[3] = fma2(va, w1.y, acc0[3]);  acc1[3] = fma2(vb, w1.y, acc1[3]);
                acc0[4] = fma2(va, w2.x, acc0[4]);  acc1[4] = fma2(vb, w2.x, acc1[4]);
                acc0[5] = fma2(va, w2.y, acc0[5]);  acc1[5] = fma2(vb, w2.y, acc1[5]);
                acc0[6] = fma2(va, w3.x, acc0[6]);  acc1[6] = fma2(vb, w3.x, acc1[6]);
                acc0[7] = fma2(va, w3.y, acc0[7]);  acc1[7] = fma2(vb, w3.y, acc1[7]);
                acc0[8] = fma2(va, w4.x, acc0[8]);  acc1[8] = fma2(vb, w4.x, acc1[8]);
                acc0[9] = fma2(va, w4.y, acc0[9]);  acc1[9] = fma2(vb, w4.y, acc1[9]);
            }
        }
        __syncthreads();
        if (c + 2 < c1) issue(c + 2);
        asm volatile("cp.async.commit_group;");
    }

    // epilogue: store both rows (guard tail)
#pragma unroll
    for (int half = 0; half < 2; half++) {
        size_t r = rowBase + tid + half * 128;
        if (r >= NROW_TOT) break;
        ull* accp = half ? acc1 : acc0;
        int b = (int)(r / T_N);
        int t = (int)(r % T_N);
        float* outp = syn + (size_t)b * SUB * T_N + t;
#pragma unroll
        for (int p = 0; p < 10; p++) {
            float h0, h1; unpack2(accp[p], h0, h1);
            outp[(size_t)(2 * p) * T_N] = h0;
            outp[(size_t)(2 * p + 1) * T_N] = h1;
        }
    }
}

// ---------------- kernel 4: 200-tap causal conv (e+i) + tanh + layer2 reduce ----------------
// Block: 256 threads, tile of 1024 t (4 per thread, strided by 256).
// syn_e assembled from 3 K-split partials during load; values pre-packed (v,v).
#define CTILE 1024
#define CHALO 199
#define CSME (CTILE + CHALO)   // 1223

__global__ void __launch_bounds__(256, 3) conv_kernel(float* __restrict__ dout, int out_size)
{
    __shared__ __align__(16) ull sE[CSME];
    __shared__ __align__(16) ull sI[CSME];
    __shared__ __align__(16) ull sK[TNO * 10];
    int tid = threadIdx.x;
    int s = blockIdx.y, b = blockIdx.z;
    int t0 = blockIdx.x * CTILE;

    size_t chan = (size_t)(b * SUB + s) * T_N;
    const float* pe0 = g_syn_ep[0] + chan;
    const float* pe1 = g_syn_ep[1] + chan;
    const float* pe2 = g_syn_ep[2] + chan;
    const float* si  = g_syn_i + chan;
    for (int l = tid; l < CSME; l += 256) {
        int t = t0 - CHALO + l;
        bool ok = (t >= 0 && t < T_N);
        float ve = ok ? (pe0[t] + pe1[t] + pe2[t]) : 0.f;
        float vi = ok ? si[t] : 0.f;
        sE[l] = pack2(ve, ve);
        sI[l] = pack2(vi, vi);
    }
    const ull* Kg = g_Kp + (size_t)s * (TNO * 10);
    for (int l = tid; l < TNO * 10; l += 256) sK[l] = Kg[l];
    __syncthreads();

    ull acc[4][5];
#pragma unroll
    for (int j = 0; j < 4; j++)
#pragma unroll
        for (int p = 0; p < 5; p++) acc[j][p] = g_biasP[s * 5 + p];

    int l0 = CHALO + tid;   // entry for (j=0, d=0); t_j entry = l0 + j*256 - d

#pragma unroll 2
    for (int d = 0; d < TNO; d++) {
        const ulonglong2* kp = reinterpret_cast<const ulonglong2*>(&sK[d * 10]);
        ulonglong2 k01 = kp[0], k23 = kp[1], k45 = kp[2], k67 = kp[3], k89 = kp[4];
#pragma unroll
        for (int j = 0; j < 4; j++) {
            int li = l0 + j * 256 - d;
            ull ve = sE[li];
            ull vi = sI[li];
            acc[j][0] = fma2(ve, k01.x, acc[j][0]);
            acc[j][1] = fma2(ve, k01.y, acc[j][1]);
            acc[j][2] = fma2(ve, k23.x, acc[j][2]);
            acc[j][3] = fma2(ve, k23.y, acc[j][3]);
            acc[j][4] = fma2(ve, k45.x, acc[j][4]);
            acc[j][0] = fma2(vi, k45.y, acc[j][0]);
            acc[j][1] = fma2(vi, k67.x, acc[j][1]);
            acc[j][2] = fma2(vi, k67.y, acc[j][2]);
            acc[j][3] = fma2(vi, k89.x, acc[j][3]);
            acc[j][4] = fma2(vi, k89.y, acc[j][4]);
        }
    }

    float* subdst = (out_size == 1730000) ? (dout + 80000) : g_sub_scratch;
    float ew[10];
#pragma unroll
    for (int h = 0; h < 10; h++) ew[h] = g_expW2[s * 10 + h];

#pragma unroll
    for (int j = 0; j < 4; j++) {
        int t = t0 + tid + j * 256;
        if (t >= T_N) continue;
        float res = 0.f;
#pragma unroll
        for (int p = 0; p < 5; p++) {
            float h0, h1; unpack2(acc[j][p], h0, h1);
            res += tanhf(h0) * ew[2 * p] + tanhf(h1) * ew[2 * p + 1];
        }
        subdst[((size_t)b * T_N + t) * SUB + s] = res;
    }
}

// ---------------- kernel 5: final[b,t] = sum_s sub_out + V_o ----------------
__global__ void final_kernel(float* dout, int out_size, const float* __restrict__ Vo)
{
    int idx = blockIdx.x * blockDim.x + threadIdx.x;
    if (idx >= B_N * T_N) return;
    const float* src = (out_size == 1730000) ? (dout + 80000) : g_sub_scratch;
    const float4* p = reinterpret_cast<const float4*>(src + (size_t)idx * SUB);
    float sum = 0.f;
#pragma unroll
    for (int i = 0; i < 5; i++) {
        float4 v = p[i];
        sum += v.x + v.y + v.z + v.w;
    }
    dout[idx] = sum + Vo[0];
}

// ---------------- launch ----------------
extern "C" void kernel_launch(void* const* d_in, const int* in_sizes, int n_in,
                              void* d_out, int out_size)
{
    const float* S_e     = (const float*)d_in[0];
    const float* S_i     = (const float*)d_in[1];
    const int*   testp   = (const int*)  d_in[3];
    const float* g_e     = (const float*)d_in[4];
    const float* g_i     = (const float*)d_in[5];
    const float* E_scale = (const float*)d_in[6];
    const float* I_scale = (const float*)d_in[7];
    const float* We      = (const float*)d_in[8];
    const float* Wi      = (const float*)d_in[9];
    const float* W2      = (const float*)d_in[10];
    const float* b1      = (const float*)d_in[11];
    const float* Ce      = (const float*)d_in[12];
    const float* Ci      = (const float*)d_in[13];
    const float* Vo      = (const float*)d_in[14];
    float* out = (float*)d_out;

    softmax_kernel<<<(E_N + 127) / 128, 128>>>(Ce, g_e, E_scale, testp, E_N, 1, out, out_size);
    softmax_kernel<<<(I_N + 127) / 128, 128>>>(Ci, g_i, I_scale, testp, I_N, 0, out, out_size);
    prep_kernel<<<(SUB * TNO * 10 + 255) / 256, 256>>>(We, Wi, W2, b1);
    dim3 gg((NROW_TOT + GROWS - 1) / GROWS, 4);
    gemm_kernel<<<gg, 128>>>(S_e, S_i);
    dim3 cg((T_N + CTILE - 1) / CTILE, SUB, B_N);
    conv_kernel<<<cg, 256>>>(out, out_size);
    final_kernel<<<(B_N * T_N + 255) / 256, 256>>>(out, out_size, Vo);
}